// round 8
// baseline (speedup 1.0000x reference)
#include <cuda_runtime.h>
#include <cuda_fp16.h>
#include <cstdint>

// Problem constants
#define EDIM   512
#define NROWS  4096      // B*L = 2*2048 (flat rows)
#define CH     128       // attention chunk length
#define NC     16        // LSEQ / CH
#define NH     16        // B * n_head = 2*8
#define HD     64        // head dim

// Scratch (device globals: no allocations allowed)
__device__ float g_q[NROWS * EDIM];
__device__ float g_k[NROWS * EDIM];
__device__ float g_v[NROWS * EDIM];
__device__ float g_o[NROWS * EDIM];
__device__ float g_kv[NH * NC * HD * HD];   // per-chunk KV states, stored as ST[m][d]
__device__ float g_sumsq_q[NROWS * 4];      // per (row, colTile) partial sum of squares
__device__ float g_sumsq_k[NROWS * 4];
__device__ int   g_ready[NH * NC];          // chunk-state ready flags

// ----------------------------------------------------------------------------
// fp16 helpers
// ----------------------------------------------------------------------------
__device__ __forceinline__ unsigned pk(float x, float y) {
    __half2 h = __floats2half2_rn(x, y);
    return *(unsigned*)&h;
}

__device__ __forceinline__ void mma_f16(float* c, const unsigned* a, const unsigned* b) {
    asm volatile(
        "mma.sync.aligned.m16n8k16.row.col.f32.f16.f16.f32 "
        "{%0,%1,%2,%3}, {%4,%5,%6,%7}, {%8,%9}, {%0,%1,%2,%3};"
        : "+f"(c[0]), "+f"(c[1]), "+f"(c[2]), "+f"(c[3])
        : "r"(a[0]), "r"(a[1]), "r"(a[2]), "r"(a[3]), "r"(b[0]), "r"(b[1]));
}

__device__ __forceinline__ uint32_t smem_u32(const void* p) {
    uint32_t a;
    asm("{ .reg .u64 tmp; cvta.to.shared.u64 tmp, %1; cvt.u32.u64 %0, tmp; }"
        : "=r"(a) : "l"(p));
    return a;
}

#define LDSM4(r0, r1, r2, r3, addr) \
    asm volatile("ldmatrix.sync.aligned.m8n8.x4.shared.b16 {%0,%1,%2,%3}, [%4];" \
        : "=r"(r0), "=r"(r1), "=r"(r2), "=r"(r3) : "r"(addr))

// ----------------------------------------------------------------------------
// fp16 tensor-core GEMM (NT): C[i][j] = act( sum_e A[i][e] * W[j][e] + bias[j] )
// Block tile 128x128, K-tile 32 (2 x k16), 256 threads = 8 warps, warp 64x32.
// Double-buffered smem (2 x 20KB), ldmatrix fragment loads, 1 sync per K-tile.
// Epilogue: bias + relu + deterministic per-row sumsq partials (sel 0/1).
// ----------------------------------------------------------------------------
__device__ __forceinline__ void gemm_body(
    const float* __restrict__ A, const float* __restrict__ W,
    const float* __restrict__ bias, float* __restrict__ C,
    int rowBase, int colBase, bool relu, int sel)
{
    __shared__ unsigned As[2][128 * 20];
    __shared__ unsigned Bs[2][128 * 20];

    const int t    = threadIdx.x;
    const int lane = t & 31;
    const int warp = t >> 5;
    const int wm   = (warp >> 2) * 64;
    const int wn   = (warp & 3) * 32;
    const int g    = lane >> 2;
    const int tg   = lane & 3;
    const int sub  = lane >> 3;
    const int li   = lane & 7;

    const uint32_t asb = smem_u32(&As[0][0]);
    const uint32_t bsb = smem_u32(&Bs[0][0]);
    const uint32_t STG = 128 * 20 * 4;        // bytes per stage

    // ldmatrix base addresses (buf 0, ks 0); halves, stride 40 halves/row
    uint32_t a_ad[4], b_ad[2];
    #pragma unroll
    for (int mt = 0; mt < 4; mt++) {
        int row = wm + mt * 16 + (sub & 1) * 8 + li;
        a_ad[mt] = asb + (uint32_t)(row * 40 + (sub >> 1) * 8) * 2;
    }
    #pragma unroll
    for (int np = 0; np < 2; np++) {
        int row = wn + np * 16 + (sub >> 1) * 8 + li;
        b_ad[np] = bsb + (uint32_t)(row * 40 + (sub & 1) * 8) * 2;
    }

    // Global staging: 4 float4 per operand per thread per K-tile
    const int r0l = t >> 3;                   // 0..31
    const int kql = (t & 7) << 2;             // 0..28

    float acc[4][4][4];
    #pragma unroll
    for (int mt = 0; mt < 4; mt++)
        #pragma unroll
        for (int nt = 0; nt < 4; nt++)
            #pragma unroll
            for (int q = 0; q < 4; q++) acc[mt][nt][q] = 0.0f;

    uint2 pA[4], pB[4];

    // Prologue: stage 0 -> buf 0
    #pragma unroll
    for (int p = 0; p < 4; p++) {
        int rr = r0l + p * 32;
        float4 a = *(const float4*)&A[(size_t)(rowBase + rr) * EDIM + kql];
        float4 w = *(const float4*)&W[(size_t)(colBase + rr) * EDIM + kql];
        pA[p] = make_uint2(pk(a.x, a.y), pk(a.z, a.w));
        pB[p] = make_uint2(pk(w.x, w.y), pk(w.z, w.w));
    }
    #pragma unroll
    for (int p = 0; p < 4; p++) {
        int rr = r0l + p * 32;
        *(uint2*)&As[0][rr * 20 + (t & 7) * 2] = pA[p];
        *(uint2*)&Bs[0][rr * 20 + (t & 7) * 2] = pB[p];
    }
    __syncthreads();

    int buf = 0;
    for (int it = 0; it < EDIM / 32; it++) {
        const bool has_next = (it + 1 < EDIM / 32);
        if (has_next) {
            int k0 = (it + 1) * 32;
            #pragma unroll
            for (int p = 0; p < 4; p++) {
                int rr = r0l + p * 32;
                float4 a = *(const float4*)&A[(size_t)(rowBase + rr) * EDIM + k0 + kql];
                float4 w = *(const float4*)&W[(size_t)(colBase + rr) * EDIM + k0 + kql];
                pA[p] = make_uint2(pk(a.x, a.y), pk(a.z, a.w));
                pB[p] = make_uint2(pk(w.x, w.y), pk(w.z, w.w));
            }
        }

        const uint32_t boff = buf * STG;
        #pragma unroll
        for (int ks = 0; ks < 2; ks++) {
            const uint32_t koff = boff + ks * 32;   // 16 halves = 32 bytes
            unsigned af[4][4], bf[4][2];
            #pragma unroll
            for (int mt = 0; mt < 4; mt++)
                LDSM4(af[mt][0], af[mt][1], af[mt][2], af[mt][3], a_ad[mt] + koff);
            #pragma unroll
            for (int np = 0; np < 2; np++)
                LDSM4(bf[2 * np][0], bf[2 * np][1], bf[2 * np + 1][0], bf[2 * np + 1][1],
                      b_ad[np] + koff);
            #pragma unroll
            for (int mt = 0; mt < 4; mt++)
                #pragma unroll
                for (int nt = 0; nt < 4; nt++)
                    mma_f16(acc[mt][nt], af[mt], bf[nt]);
        }

        if (has_next) {
            const int nb = buf ^ 1;
            #pragma unroll
            for (int p = 0; p < 4; p++) {
                int rr = r0l + p * 32;
                *(uint2*)&As[nb][rr * 20 + (t & 7) * 2] = pA[p];
                *(uint2*)&Bs[nb][rr * 20 + (t & 7) * 2] = pB[p];
            }
        }
        __syncthreads();
        buf ^= 1;
    }

    // Epilogue: bias + optional relu + per-row partial sumsq
    float ssr0[4], ssr1[4];
    #pragma unroll
    for (int mt = 0; mt < 4; mt++) { ssr0[mt] = 0.0f; ssr1[mt] = 0.0f; }

    #pragma unroll
    for (int nt = 0; nt < 4; nt++) {
        int cc = colBase + wn + nt * 8 + 2 * tg;
        float bx = bias[cc], by = bias[cc + 1];
        #pragma unroll
        for (int mt = 0; mt < 4; mt++) {
            int r0 = rowBase + wm + mt * 16 + g;
            float2 v0, v1;
            v0.x = acc[mt][nt][0] + bx; v0.y = acc[mt][nt][1] + by;
            v1.x = acc[mt][nt][2] + bx; v1.y = acc[mt][nt][3] + by;
            if (relu) {
                v0.x = fmaxf(v0.x, 0.0f); v0.y = fmaxf(v0.y, 0.0f);
                v1.x = fmaxf(v1.x, 0.0f); v1.y = fmaxf(v1.y, 0.0f);
            }
            ssr0[mt] += v0.x * v0.x + v0.y * v0.y;
            ssr1[mt] += v1.x * v1.x + v1.y * v1.y;
            *(float2*)&C[(size_t)r0 * EDIM + cc]       = v0;
            *(float2*)&C[(size_t)(r0 + 8) * EDIM + cc] = v1;
        }
    }

    if (sel <= 1) {
        #pragma unroll
        for (int mt = 0; mt < 4; mt++) {
            #pragma unroll
            for (int o = 1; o < 4; o <<= 1) {
                ssr0[mt] += __shfl_xor_sync(0xffffffffu, ssr0[mt], o);
                ssr1[mt] += __shfl_xor_sync(0xffffffffu, ssr1[mt], o);
            }
        }
        __syncthreads();
        float* red = (float*)As;
        if (tg == 0) {
            #pragma unroll
            for (int mt = 0; mt < 4; mt++) {
                int rl = wm + mt * 16 + g;
                red[(warp & 3) * 128 + rl]     = ssr0[mt];
                red[(warp & 3) * 128 + rl + 8] = ssr1[mt];
            }
        }
        __syncthreads();
        if (t < 128) {
            float s = red[t] + red[128 + t] + red[256 + t] + red[384 + t];
            float* dst = (sel == 0) ? g_sumsq_q : g_sumsq_k;
            dst[(rowBase + t) * 4 + (colBase >> 7)] = s;
        }
    }
}

__global__ void __launch_bounds__(256, 2) qkv_gemm(
    const float* __restrict__ X,
    const float* __restrict__ Wq, const float* __restrict__ bq,
    const float* __restrict__ Wk, const float* __restrict__ bk,
    const float* __restrict__ Wv, const float* __restrict__ bv)
{
    // Reset chunk-state flags each replay (stream-ordered before chunk_attn).
    if (blockIdx.x == 0 && blockIdx.y == 0 && blockIdx.z == 0 && threadIdx.x < NH * NC)
        g_ready[threadIdx.x] = 0;

    int rowBase = blockIdx.x * 128;
    int colBase = blockIdx.y * 128;
    int which   = blockIdx.z;
    if (which == 0)      gemm_body(X, Wq, bq, g_q, rowBase, colBase, true, 0);
    else if (which == 1) gemm_body(X, Wk, bk, g_k, rowBase, colBase, true, 1);
    else                 gemm_body(X, Wv, bv, g_v, rowBase, colBase, false, 2);
}

__global__ void __launch_bounds__(256, 2) oproj_gemm(
    const float* __restrict__ Wo, const float* __restrict__ bo,
    float* __restrict__ out)
{
    gemm_body(g_o, Wo, bo, out, blockIdx.x * 128, blockIdx.y * 128, false, 2);
}

// ----------------------------------------------------------------------------
// Fused attention (unchanged from round 7, which passed at 76.3us)
// ----------------------------------------------------------------------------
#define ATTN_W_QS 0
#define ATTN_W_KS 4608
#define ATTN_W_VT 9216
#define ATTN_W_PT 13568
#define ATTN_W_SS 15872
#define ATTN_W_SC 24576
#define CHUNK_ATTN_SMEM ((24576 + 256) * 4)

__global__ void __launch_bounds__(256, 2) chunk_attn()
{
    int c = blockIdx.x, n = blockIdx.y;
    int b = n >> 3, h = n & 7;
    extern __shared__ unsigned smu[];
    unsigned* Qs = smu + ATTN_W_QS;         // [128][36] h2
    unsigned* Ks = smu + ATTN_W_KS;         // [128][36] h2
    unsigned* Vt = smu + ATTN_W_VT;         // [64][68] h2 (transposed)
    unsigned* Pt = smu + ATTN_W_PT;         // [64][36] h2
    unsigned* Ss = smu + ATTN_W_SS;         // [128][68] h2
    unsigned* Kt = Ss;                      // [64][68] h2 alias (dead before pass1)
    float* ks_s  = (float*)(smu + ATTN_W_SC);
    float* qs_s  = ks_s + 128;
    __half* Vt_h = (__half*)Vt;
    __half* Kt_h = (__half*)Kt;
    int t = threadIdx.x;
    int lane = t & 31, w = t >> 5;
    int g = lane >> 2, tg = lane & 3;

    // phase 0: per-row reciprocal norms
    {
        int row = t & 127;
        int rr  = (c * CH + row) * 2 + b;
        const float* s = ((t < 128) ? g_sumsq_k : g_sumsq_q) + rr * 4;
        float sc = 1.0f / fmaxf(sqrtf(s[0] + s[1] + s[2] + s[3]), 1e-12f);
        ((t < 128) ? ks_s : qs_s)[row] = sc;
    }
    __syncthreads();

    // phase 1: tile loads
    #pragma unroll
    for (int p = 0; p < 8; p++) {
        int idx = t + p * 256;
        int row = idx >> 4;
        int d0  = (idx & 15) << 2;
        int rr  = (c * CH + row) * 2 + b;
        size_t gg = (size_t)rr * EDIM + h * HD + d0;
        float sq = qs_s[row];
        float sk = ks_s[row];
        float4 qv = *(const float4*)&g_q[gg];
        Qs[row * 36 + (d0 >> 1)]     = pk(qv.x * sq, qv.y * sq);
        Qs[row * 36 + (d0 >> 1) + 1] = pk(qv.z * sq, qv.w * sq);
        float4 kk = *(const float4*)&g_k[gg];
        float kx = kk.x * sk, ky = kk.y * sk, kz = kk.z * sk, kw = kk.w * sk;
        Ks[row * 36 + (d0 >> 1)]     = pk(kx, ky);
        Ks[row * 36 + (d0 >> 1) + 1] = pk(kz, kw);
        Kt_h[(d0 + 0) * 136 + row] = __float2half_rn(kx);
        Kt_h[(d0 + 1) * 136 + row] = __float2half_rn(ky);
        Kt_h[(d0 + 2) * 136 + row] = __float2half_rn(kz);
        Kt_h[(d0 + 3) * 136 + row] = __float2half_rn(kw);
        float4 vv = *(const float4*)&g_v[gg];
        Vt_h[(d0 + 0) * 136 + row] = __float2half_rn(vv.x);
        Vt_h[(d0 + 1) * 136 + row] = __float2half_rn(vv.y);
        Vt_h[(d0 + 2) * 136 + row] = __float2half_rn(vv.z);
        Vt_h[(d0 + 3) * 136 + row] = __float2half_rn(vv.w);
    }
    __syncthreads();

    // phase 2: S_c[m][d] = sum_j V[j][m] * K[j][d]
    {
        int m0 = (w & 3) * 16;
        int nb = (w >> 2) * 32;
        float acc[4][4];
        #pragma unroll
        for (int i = 0; i < 4; i++)
            #pragma unroll
            for (int j = 0; j < 4; j++) acc[i][j] = 0.0f;

        #pragma unroll
        for (int ks = 0; ks < 8; ks++) {
            int k8 = ks * 8;
            unsigned a[4];
            a[0] = Vt[(m0 + g) * 68 + k8 + tg];
            a[1] = Vt[(m0 + g + 8) * 68 + k8 + tg];
            a[2] = Vt[(m0 + g) * 68 + k8 + tg + 4];
            a[3] = Vt[(m0 + g + 8) * 68 + k8 + tg + 4];
            #pragma unroll
            for (int nt = 0; nt < 4; nt++) {
                unsigned bf[2];
                bf[0] = Kt[(nb + nt * 8 + g) * 68 + k8 + tg];
                bf[1] = Kt[(nb + nt * 8 + g) * 68 + k8 + tg + 4];
                mma_f16(acc[nt], a, bf);
            }
        }
        float* outp = &g_kv[((size_t)n * NC + c) * HD * HD];
        #pragma unroll
        for (int nt = 0; nt < 4; nt++) {
            int cc = nb + nt * 8 + 2 * tg;
            *(float2*)&outp[(m0 + g) * HD + cc]     = make_float2(acc[nt][0], acc[nt][1]);
            *(float2*)&outp[(m0 + g + 8) * HD + cc] = make_float2(acc[nt][2], acc[nt][3]);
        }
    }
    __threadfence();
    __syncthreads();
    if (t == 0) atomicExch(&g_ready[n * NC + c], 1);

    // phase 3: wait for prior chunks, sum prefix (fp32 -> fp16)
    if (t < c) {
        while (atomicAdd(&g_ready[n * NC + t], 0) == 0) { }
    }
    __syncthreads();
    __threadfence();
    #pragma unroll
    for (int p = 0; p < 4; p++) {
        int slot = t + p * 256;
        int m  = slot >> 4;
        int d0 = (slot & 15) << 2;
        float4 s = make_float4(0.0f, 0.0f, 0.0f, 0.0f);
        for (int c2 = 0; c2 < c; c2++) {
            float4 v = *(const float4*)&g_kv[((size_t)n * NC + c2) * HD * HD + m * HD + d0];
            s.x += v.x; s.y += v.y; s.z += v.z; s.w += v.w;
        }
        Pt[m * 36 + (d0 >> 1)]     = pk(s.x, s.y);
        Pt[m * 36 + (d0 >> 1) + 1] = pk(s.z, s.w);
    }
    __syncthreads();   // Pt ready; Kt region now dead -> pass1 may write Ss

    // Warp-balanced causal row-block assignment
    const int rb = (w < 4) ? w : 11 - w;
    const int i0 = rb * 16;
    const int r0 = i0 + g, r1 = i0 + g + 8;
    const int ntmax = 2 * rb + 1;

    // phase 4: S = causal(Q K^T), only non-fully-masked tiles
    {
        float acc1[16][4];
        #pragma unroll
        for (int nt = 0; nt < 16; nt++)
            #pragma unroll
            for (int q = 0; q < 4; q++) acc1[nt][q] = 0.0f;

        #pragma unroll
        for (int ks = 0; ks < 4; ks++) {
            int k8 = ks * 8;
            unsigned a[4];
            a[0] = Qs[r0 * 36 + k8 + tg];
            a[1] = Qs[r1 * 36 + k8 + tg];
            a[2] = Qs[r0 * 36 + k8 + tg + 4];
            a[3] = Qs[r1 * 36 + k8 + tg + 4];
            #pragma unroll
            for (int nt = 0; nt < 16; nt++) {
                if (nt <= ntmax) {
                    unsigned bf[2];
                    bf[0] = Ks[(nt * 8 + g) * 36 + k8 + tg];
                    bf[1] = Ks[(nt * 8 + g) * 36 + k8 + tg + 4];
                    mma_f16(acc1[nt], a, bf);
                }
            }
        }
        #pragma unroll
        for (int nt = 0; nt < 16; nt++) {
            if (nt <= ntmax) {
                int j0 = nt * 8 + 2 * tg;
                Ss[r0 * 68 + nt * 4 + tg] = pk(j0 <= r0 ? acc1[nt][0] : 0.0f,
                                               j0 + 1 <= r0 ? acc1[nt][1] : 0.0f);
                Ss[r1 * 68 + nt * 4 + tg] = pk(j0 <= r1 ? acc1[nt][2] : 0.0f,
                                               j0 + 1 <= r1 ? acc1[nt][3] : 0.0f);
            }
        }
    }
    __syncwarp();   // each warp reads only its own Ss rows

    // phase 5: out = Q @ Pt + Ss @ Vt
    {
        float acc2[8][4];
        #pragma unroll
        for (int nt = 0; nt < 8; nt++)
            #pragma unroll
            for (int q = 0; q < 4; q++) acc2[nt][q] = 0.0f;

        #pragma unroll
        for (int ks = 0; ks < 4; ks++) {            // Q @ P, k = 64
            int k8 = ks * 8;
            unsigned a[4];
            a[0] = Qs[r0 * 36 + k8 + tg];
            a[1] = Qs[r1 * 36 + k8 + tg];
            a[2] = Qs[r0 * 36 + k8 + tg + 4];
            a[3] = Qs[r1 * 36 + k8 + tg + 4];
            #pragma unroll
            for (int nt = 0; nt < 8; nt++) {
                unsigned bf[2];
                bf[0] = Pt[(nt * 8 + g) * 36 + k8 + tg];
                bf[1] = Pt[(nt * 8 + g) * 36 + k8 + tg + 4];
                mma_f16(acc2[nt], a, bf);
            }
        }
        #pragma unroll
        for (int ks = 0; ks < 8; ks++) {            // S @ V, k <= (rb+1)*16
            if (ks <= rb) {
                int k8 = ks * 8;
                unsigned a[4];
                a[0] = Ss[r0 * 68 + k8 + tg];
                a[1] = Ss[r1 * 68 + k8 + tg];
                a[2] = Ss[r0 * 68 + k8 + tg + 4];
                a[3] = Ss[r1 * 68 + k8 + tg + 4];
                #pragma unroll
                for (int nt = 0; nt < 8; nt++) {
                    unsigned bf[2];
                    bf[0] = Vt[(nt * 8 + g) * 68 + k8 + tg];
                    bf[1] = Vt[(nt * 8 + g) * 68 + k8 + tg + 4];
                    mma_f16(acc2[nt], a, bf);
                }
            }
        }

        #pragma unroll
        for (int nt = 0; nt < 8; nt++) {
            int cc = nt * 8 + 2 * tg;
            int l0 = (c * CH + r0) * 2 + b;
            int l1 = (c * CH + r1) * 2 + b;
            *(float2*)&g_o[(size_t)l0 * EDIM + h * HD + cc] = make_float2(acc2[nt][0], acc2[nt][1]);
            *(float2*)&g_o[(size_t)l1 * EDIM + h * HD + cc] = make_float2(acc2[nt][2], acc2[nt][3]);
        }
    }
}

// ----------------------------------------------------------------------------
extern "C" void kernel_launch(void* const* d_in, const int* in_sizes, int n_in,
                              void* d_out, int out_size)
{
    const float* X  = (const float*)d_in[0];
    const float* Wq = (const float*)d_in[1];
    const float* bq = (const float*)d_in[2];
    const float* Wk = (const float*)d_in[3];
    const float* bk = (const float*)d_in[4];
    const float* Wv = (const float*)d_in[5];
    const float* bv = (const float*)d_in[6];
    const float* Wo = (const float*)d_in[7];
    const float* bo = (const float*)d_in[8];
    float* out = (float*)d_out;

    (void)in_sizes; (void)n_in; (void)out_size;

    cudaFuncSetAttribute(chunk_attn, cudaFuncAttributeMaxDynamicSharedMemorySize, CHUNK_ATTN_SMEM);

    qkv_gemm<<<dim3(32, 4, 3), 256>>>(X, Wq, bq, Wk, bk, Wv, bv);
    chunk_attn<<<dim3(NC, NH), 256, CHUNK_ATTN_SMEM>>>();
    oproj_gemm<<<dim3(32, 4), 256>>>(Wo, bo, out);
}

// round 13
// speedup vs baseline: 1.0475x; 1.0475x over previous
#include <cuda_runtime.h>
#include <cuda_fp16.h>
#include <cstdint>

// Problem constants
#define EDIM   512
#define NROWS  4096      // B*L = 2*2048 (flat rows)
#define CH     128       // attention chunk length
#define NC     16        // LSEQ / CH
#define NH     16        // B * n_head = 2*8
#define HD     64        // head dim

// Scratch (device globals: no allocations allowed)
__device__ __half g_qh[NROWS * EDIM];       // fp16 q (unscaled)
__device__ __half g_kh[NROWS * EDIM];       // fp16 k (unscaled)
__device__ __half g_vh[NROWS * EDIM];       // fp16 v
__device__ float  g_o[NROWS * EDIM];        // fp32 attention output
__device__ float  g_kv[NH * NC * HD * HD];  // per-chunk KV states, ST[m][d]
__device__ float  g_sumsq_q[NROWS * 4];     // per (row, colTile) partial sum of squares
__device__ float  g_sumsq_k[NROWS * 4];
__device__ int    g_ready[NH * NC];         // chunk-state ready flags

// ----------------------------------------------------------------------------
// fp16 helpers
// ----------------------------------------------------------------------------
__device__ __forceinline__ unsigned pk(float x, float y) {
    __half2 h = __floats2half2_rn(x, y);
    return *(unsigned*)&h;
}

__device__ __forceinline__ void mma_f16(float* c, const unsigned* a, const unsigned* b) {
    asm volatile(
        "mma.sync.aligned.m16n8k16.row.col.f32.f16.f16.f32 "
        "{%0,%1,%2,%3}, {%4,%5,%6,%7}, {%8,%9}, {%0,%1,%2,%3};"
        : "+f"(c[0]), "+f"(c[1]), "+f"(c[2]), "+f"(c[3])
        : "r"(a[0]), "r"(a[1]), "r"(a[2]), "r"(a[3]), "r"(b[0]), "r"(b[1]));
}

// ----------------------------------------------------------------------------
// fp16 tensor-core GEMM (NT): C[i][j] = act( sum_e A[i][e] * W[j][e] + bias[j] )
// Block tile 128x128, K-tile 32 (2 x k16 steps), 256 threads = 8 warps,
// warp tile 64x32, register-staged single-smem-buffer pipeline (R7-proven).
// Output: fp16 (Ch != null) or fp32 (C). Epilogue sumsq partials for sel 0/1.
// ----------------------------------------------------------------------------
__device__ __forceinline__ void gemm_body(
    const float* __restrict__ A, const float* __restrict__ W,
    const float* __restrict__ bias, float* __restrict__ C, __half* __restrict__ Ch,
    int rowBase, int colBase, bool relu, int sel)
{
    __shared__ unsigned As[128 * 20];
    __shared__ unsigned Bs[128 * 20];

    const int t    = threadIdx.x;
    const int lane = t & 31;
    const int warp = t >> 5;
    const int wm   = (warp >> 2) * 64;
    const int wn   = (warp & 3) * 32;
    const int g    = lane >> 2;
    const int tg   = lane & 3;

    float acc[4][4][4];
    #pragma unroll
    for (int mt = 0; mt < 4; mt++)
        #pragma unroll
        for (int nt = 0; nt < 4; nt++)
            #pragma unroll
            for (int q = 0; q < 4; q++) acc[mt][nt][q] = 0.0f;

    float4 stA[4], stB[4];

    #pragma unroll
    for (int p = 0; p < 4; p++) {
        int idx = t + p * 256;
        int r   = idx >> 3;
        int kq  = (idx & 7) << 2;
        stA[p] = *(const float4*)&A[(size_t)(rowBase + r) * EDIM + kq];
        stB[p] = *(const float4*)&W[(size_t)(colBase + r) * EDIM + kq];
    }
    #pragma unroll
    for (int p = 0; p < 4; p++) {
        int idx = t + p * 256;
        int r   = idx >> 3;
        int c2  = (idx & 7) << 1;
        As[r * 20 + c2]     = pk(stA[p].x, stA[p].y);
        As[r * 20 + c2 + 1] = pk(stA[p].z, stA[p].w);
        Bs[r * 20 + c2]     = pk(stB[p].x, stB[p].y);
        Bs[r * 20 + c2 + 1] = pk(stB[p].z, stB[p].w);
    }
    __syncthreads();

    for (int it = 0; it < EDIM / 32; it++) {
        const bool has_next = (it + 1 < EDIM / 32);
        if (has_next) {
            int k0 = (it + 1) * 32;
            #pragma unroll
            for (int p = 0; p < 4; p++) {
                int idx = t + p * 256;
                int r   = idx >> 3;
                int kq  = (idx & 7) << 2;
                stA[p] = *(const float4*)&A[(size_t)(rowBase + r) * EDIM + k0 + kq];
                stB[p] = *(const float4*)&W[(size_t)(colBase + r) * EDIM + k0 + kq];
            }
        }

        #pragma unroll
        for (int ks = 0; ks < 2; ks++) {
            const int k8 = ks * 8;
            unsigned af[4][4], bf[4][2];
            #pragma unroll
            for (int mt = 0; mt < 4; mt++) {
                int row = wm + mt * 16 + g;
                af[mt][0] = As[row * 20 + k8 + tg];
                af[mt][1] = As[(row + 8) * 20 + k8 + tg];
                af[mt][2] = As[row * 20 + k8 + tg + 4];
                af[mt][3] = As[(row + 8) * 20 + k8 + tg + 4];
            }
            #pragma unroll
            for (int nt = 0; nt < 4; nt++) {
                int nr = wn + nt * 8 + g;
                bf[nt][0] = Bs[nr * 20 + k8 + tg];
                bf[nt][1] = Bs[nr * 20 + k8 + tg + 4];
            }
            #pragma unroll
            for (int mt = 0; mt < 4; mt++)
                #pragma unroll
                for (int nt = 0; nt < 4; nt++)
                    mma_f16(acc[mt][nt], af[mt], bf[nt]);
        }

        if (has_next) {
            __syncthreads();
            #pragma unroll
            for (int p = 0; p < 4; p++) {
                int idx = t + p * 256;
                int r   = idx >> 3;
                int c2  = (idx & 7) << 1;
                As[r * 20 + c2]     = pk(stA[p].x, stA[p].y);
                As[r * 20 + c2 + 1] = pk(stA[p].z, stA[p].w);
                Bs[r * 20 + c2]     = pk(stB[p].x, stB[p].y);
                Bs[r * 20 + c2 + 1] = pk(stB[p].z, stB[p].w);
            }
            __syncthreads();
        }
    }

    // Epilogue: bias + optional relu + per-row partial sumsq; fp16 or fp32 store
    float ssr0[4], ssr1[4];
    #pragma unroll
    for (int mt = 0; mt < 4; mt++) { ssr0[mt] = 0.0f; ssr1[mt] = 0.0f; }

    #pragma unroll
    for (int nt = 0; nt < 4; nt++) {
        int cc = colBase + wn + nt * 8 + 2 * tg;
        float bx = bias[cc], by = bias[cc + 1];
        #pragma unroll
        for (int mt = 0; mt < 4; mt++) {
            int r0 = rowBase + wm + mt * 16 + g;
            float2 v0, v1;
            v0.x = acc[mt][nt][0] + bx; v0.y = acc[mt][nt][1] + by;
            v1.x = acc[mt][nt][2] + bx; v1.y = acc[mt][nt][3] + by;
            if (relu) {
                v0.x = fmaxf(v0.x, 0.0f); v0.y = fmaxf(v0.y, 0.0f);
                v1.x = fmaxf(v1.x, 0.0f); v1.y = fmaxf(v1.y, 0.0f);
            }
            ssr0[mt] += v0.x * v0.x + v0.y * v0.y;
            ssr1[mt] += v1.x * v1.x + v1.y * v1.y;
            if (Ch) {
                *(unsigned*)&Ch[(size_t)r0 * EDIM + cc]       = pk(v0.x, v0.y);
                *(unsigned*)&Ch[(size_t)(r0 + 8) * EDIM + cc] = pk(v1.x, v1.y);
            } else {
                *(float2*)&C[(size_t)r0 * EDIM + cc]       = v0;
                *(float2*)&C[(size_t)(r0 + 8) * EDIM + cc] = v1;
            }
        }
    }

    if (sel <= 1) {
        #pragma unroll
        for (int mt = 0; mt < 4; mt++) {
            #pragma unroll
            for (int o = 1; o < 4; o <<= 1) {
                ssr0[mt] += __shfl_xor_sync(0xffffffffu, ssr0[mt], o);
                ssr1[mt] += __shfl_xor_sync(0xffffffffu, ssr1[mt], o);
            }
        }
        __syncthreads();
        float* red = (float*)As;
        if (tg == 0) {
            #pragma unroll
            for (int mt = 0; mt < 4; mt++) {
                int rl = wm + mt * 16 + g;
                red[(warp & 3) * 128 + rl]     = ssr0[mt];
                red[(warp & 3) * 128 + rl + 8] = ssr1[mt];
            }
        }
        __syncthreads();
        if (t < 128) {
            float s = red[t] + red[128 + t] + red[256 + t] + red[384 + t];
            float* dst = (sel == 0) ? g_sumsq_q : g_sumsq_k;
            dst[(rowBase + t) * 4 + (colBase >> 7)] = s;
        }
    }
}

__global__ void __launch_bounds__(256) qkv_gemm(
    const float* __restrict__ X,
    const float* __restrict__ Wq, const float* __restrict__ bq,
    const float* __restrict__ Wk, const float* __restrict__ bk,
    const float* __restrict__ Wv, const float* __restrict__ bv)
{
    // Reset chunk-state flags each replay (stream-ordered before chunk_attn).
    if (blockIdx.x == 0 && blockIdx.y == 0 && blockIdx.z == 0 && threadIdx.x < NH * NC)
        g_ready[threadIdx.x] = 0;

    int rowBase = blockIdx.x * 128;
    int colBase = blockIdx.y * 128;
    int which   = blockIdx.z;
    if (which == 0)      gemm_body(X, Wq, bq, nullptr, g_qh, rowBase, colBase, true, 0);
    else if (which == 1) gemm_body(X, Wk, bk, nullptr, g_kh, rowBase, colBase, true, 1);
    else                 gemm_body(X, Wv, bv, nullptr, g_vh, rowBase, colBase, false, 2);
}

__global__ void __launch_bounds__(256) oproj_gemm(
    const float* __restrict__ Wo, const float* __restrict__ bo,
    float* __restrict__ out)
{
    gemm_body(g_o, Wo, bo, out, nullptr, blockIdx.x * 128, blockIdx.y * 128, false, 3);
}

// ----------------------------------------------------------------------------
// Fused attention (R7 structure; q/k/v now loaded as fp16, scaled via hmul2)
// ----------------------------------------------------------------------------
#define ATTN_W_QS 0
#define ATTN_W_KS 4608
#define ATTN_W_VT 9216
#define ATTN_W_PT 13568
#define ATTN_W_SS 15872
#define ATTN_W_SC 24576
#define CHUNK_ATTN_SMEM ((24576 + 256) * 4)

__global__ void __launch_bounds__(256, 2) chunk_attn()
{
    int c = blockIdx.x, n = blockIdx.y;
    int b = n >> 3, h = n & 7;
    extern __shared__ unsigned smu[];
    unsigned* Qs = smu + ATTN_W_QS;         // [128][36] h2
    unsigned* Ks = smu + ATTN_W_KS;         // [128][36] h2
    unsigned* Vt = smu + ATTN_W_VT;         // [64][68] h2 (transposed)
    unsigned* Pt = smu + ATTN_W_PT;         // [64][36] h2
    unsigned* Ss = smu + ATTN_W_SS;         // [128][68] h2
    unsigned* Kt = Ss;                      // [64][68] h2 alias (dead before pass1)
    float* ks_s  = (float*)(smu + ATTN_W_SC);
    float* qs_s  = ks_s + 128;
    __half* Vt_h = (__half*)Vt;
    __half* Kt_h = (__half*)Kt;
    int t = threadIdx.x;
    int lane = t & 31, w = t >> 5;
    int g = lane >> 2, tg = lane & 3;

    // phase 0: per-row reciprocal norms
    {
        int row = t & 127;
        int rr  = (c * CH + row) * 2 + b;
        const float* s = ((t < 128) ? g_sumsq_k : g_sumsq_q) + rr * 4;
        float sc = 1.0f / fmaxf(sqrtf(s[0] + s[1] + s[2] + s[3]), 1e-12f);
        ((t < 128) ? ks_s : qs_s)[row] = sc;
    }
    __syncthreads();

    // phase 1: tile loads (fp16 globals, scale q/k via hmul2)
    #pragma unroll
    for (int p = 0; p < 8; p++) {
        int idx = t + p * 256;
        int row = idx >> 4;
        int d0  = (idx & 15) << 2;
        int rr  = (c * CH + row) * 2 + b;
        size_t gg = (size_t)rr * EDIM + h * HD + d0;
        __half2 sq2 = __float2half2_rn(qs_s[row]);
        __half2 sk2 = __float2half2_rn(ks_s[row]);
        uint2 qv = *(const uint2*)&g_qh[gg];
        __half2 q0 = __hmul2(*(__half2*)&qv.x, sq2);
        __half2 q1 = __hmul2(*(__half2*)&qv.y, sq2);
        Qs[row * 36 + (d0 >> 1)]     = *(unsigned*)&q0;
        Qs[row * 36 + (d0 >> 1) + 1] = *(unsigned*)&q1;
        uint2 kv = *(const uint2*)&g_kh[gg];
        __half2 k0 = __hmul2(*(__half2*)&kv.x, sk2);
        __half2 k1 = __hmul2(*(__half2*)&kv.y, sk2);
        Ks[row * 36 + (d0 >> 1)]     = *(unsigned*)&k0;
        Ks[row * 36 + (d0 >> 1) + 1] = *(unsigned*)&k1;
        Kt_h[(d0 + 0) * 136 + row] = __low2half(k0);
        Kt_h[(d0 + 1) * 136 + row] = __high2half(k0);
        Kt_h[(d0 + 2) * 136 + row] = __low2half(k1);
        Kt_h[(d0 + 3) * 136 + row] = __high2half(k1);
        uint2 vv = *(const uint2*)&g_vh[gg];
        __half2 v0 = *(__half2*)&vv.x;
        __half2 v1 = *(__half2*)&vv.y;
        Vt_h[(d0 + 0) * 136 + row] = __low2half(v0);
        Vt_h[(d0 + 1) * 136 + row] = __high2half(v0);
        Vt_h[(d0 + 2) * 136 + row] = __low2half(v1);
        Vt_h[(d0 + 3) * 136 + row] = __high2half(v1);
    }
    __syncthreads();

    // phase 2: S_c[m][d] = sum_j V[j][m] * K[j][d]
    {
        int m0 = (w & 3) * 16;
        int nb = (w >> 2) * 32;
        float acc[4][4];
        #pragma unroll
        for (int i = 0; i < 4; i++)
            #pragma unroll
            for (int j = 0; j < 4; j++) acc[i][j] = 0.0f;

        #pragma unroll
        for (int ks = 0; ks < 8; ks++) {
            int k8 = ks * 8;
            unsigned a[4];
            a[0] = Vt[(m0 + g) * 68 + k8 + tg];
            a[1] = Vt[(m0 + g + 8) * 68 + k8 + tg];
            a[2] = Vt[(m0 + g) * 68 + k8 + tg + 4];
            a[3] = Vt[(m0 + g + 8) * 68 + k8 + tg + 4];
            #pragma unroll
            for (int nt = 0; nt < 4; nt++) {
                unsigned bf[2];
                bf[0] = Kt[(nb + nt * 8 + g) * 68 + k8 + tg];
                bf[1] = Kt[(nb + nt * 8 + g) * 68 + k8 + tg + 4];
                mma_f16(acc[nt], a, bf);
            }
        }
        float* outp = &g_kv[((size_t)n * NC + c) * HD * HD];
        #pragma unroll
        for (int nt = 0; nt < 4; nt++) {
            int cc = nb + nt * 8 + 2 * tg;
            *(float2*)&outp[(m0 + g) * HD + cc]     = make_float2(acc[nt][0], acc[nt][1]);
            *(float2*)&outp[(m0 + g + 8) * HD + cc] = make_float2(acc[nt][2], acc[nt][3]);
        }
    }
    __threadfence();
    __syncthreads();
    if (t == 0) atomicExch(&g_ready[n * NC + c], 1);

    // phase 3: wait for prior chunks, sum prefix (fp32 -> fp16)
    if (t < c) {
        while (atomicAdd(&g_ready[n * NC + t], 0) == 0) { }
    }
    __syncthreads();
    __threadfence();
    #pragma unroll
    for (int p = 0; p < 4; p++) {
        int slot = t + p * 256;
        int m  = slot >> 4;
        int d0 = (slot & 15) << 2;
        float4 s = make_float4(0.0f, 0.0f, 0.0f, 0.0f);
        for (int c2 = 0; c2 < c; c2++) {
            float4 v = *(const float4*)&g_kv[((size_t)n * NC + c2) * HD * HD + m * HD + d0];
            s.x += v.x; s.y += v.y; s.z += v.z; s.w += v.w;
        }
        Pt[m * 36 + (d0 >> 1)]     = pk(s.x, s.y);
        Pt[m * 36 + (d0 >> 1) + 1] = pk(s.z, s.w);
    }
    __syncthreads();   // Pt ready; Kt region now dead -> pass1 may write Ss

    // Warp-balanced causal row-block assignment
    const int rb = (w < 4) ? w : 11 - w;
    const int i0 = rb * 16;
    const int r0 = i0 + g, r1 = i0 + g + 8;
    const int ntmax = 2 * rb + 1;

    // phase 4: S = causal(Q K^T), only non-fully-masked tiles
    {
        float acc1[16][4];
        #pragma unroll
        for (int nt = 0; nt < 16; nt++)
            #pragma unroll
            for (int q = 0; q < 4; q++) acc1[nt][q] = 0.0f;

        #pragma unroll
        for (int ks = 0; ks < 4; ks++) {
            int k8 = ks * 8;
            unsigned a[4];
            a[0] = Qs[r0 * 36 + k8 + tg];
            a[1] = Qs[r1 * 36 + k8 + tg];
            a[2] = Qs[r0 * 36 + k8 + tg + 4];
            a[3] = Qs[r1 * 36 + k8 + tg + 4];
            #pragma unroll
            for (int nt = 0; nt < 16; nt++) {
                if (nt <= ntmax) {
                    unsigned bf[2];
                    bf[0] = Ks[(nt * 8 + g) * 36 + k8 + tg];
                    bf[1] = Ks[(nt * 8 + g) * 36 + k8 + tg + 4];
                    mma_f16(acc1[nt], a, bf);
                }
            }
        }
        #pragma unroll
        for (int nt = 0; nt < 16; nt++) {
            if (nt <= ntmax) {
                int j0 = nt * 8 + 2 * tg;
                Ss[r0 * 68 + nt * 4 + tg] = pk(j0 <= r0 ? acc1[nt][0] : 0.0f,
                                               j0 + 1 <= r0 ? acc1[nt][1] : 0.0f);
                Ss[r1 * 68 + nt * 4 + tg] = pk(j0 <= r1 ? acc1[nt][2] : 0.0f,
                                               j0 + 1 <= r1 ? acc1[nt][3] : 0.0f);
            }
        }
    }
    __syncwarp();   // each warp reads only its own Ss rows

    // phase 5: out = Q @ Pt + Ss @ Vt
    {
        float acc2[8][4];
        #pragma unroll
        for (int nt = 0; nt < 8; nt++)
            #pragma unroll
            for (int q = 0; q < 4; q++) acc2[nt][q] = 0.0f;

        #pragma unroll
        for (int ks = 0; ks < 4; ks++) {            // Q @ P, k = 64
            int k8 = ks * 8;
            unsigned a[4];
            a[0] = Qs[r0 * 36 + k8 + tg];
            a[1] = Qs[r1 * 36 + k8 + tg];
            a[2] = Qs[r0 * 36 + k8 + tg + 4];
            a[3] = Qs[r1 * 36 + k8 + tg + 4];
            #pragma unroll
            for (int nt = 0; nt < 8; nt++) {
                unsigned bf[2];
                bf[0] = Pt[(nt * 8 + g) * 36 + k8 + tg];
                bf[1] = Pt[(nt * 8 + g) * 36 + k8 + tg + 4];
                mma_f16(acc2[nt], a, bf);
            }
        }
        #pragma unroll
        for (int ks = 0; ks < 8; ks++) {            // S @ V, k <= (rb+1)*16
            if (ks <= rb) {
                int k8 = ks * 8;
                unsigned a[4];
                a[0] = Ss[r0 * 68 + k8 + tg];
                a[1] = Ss[r1 * 68 + k8 + tg];
                a[2] = Ss[r0 * 68 + k8 + tg + 4];
                a[3] = Ss[r1 * 68 + k8 + tg + 4];
                #pragma unroll
                for (int nt = 0; nt < 8; nt++) {
                    unsigned bf[2];
                    bf[0] = Vt[(nt * 8 + g) * 68 + k8 + tg];
                    bf[1] = Vt[(nt * 8 + g) * 68 + k8 + tg + 4];
                    mma_f16(acc2[nt], a, bf);
                }
            }
        }

        #pragma unroll
        for (int nt = 0; nt < 8; nt++) {
            int cc = nt * 8 + 2 * tg;
            int l0 = (c * CH + r0) * 2 + b;
            int l1 = (c * CH + r1) * 2 + b;
            *(float2*)&g_o[(size_t)l0 * EDIM + h * HD + cc] = make_float2(acc2[nt][0], acc2[nt][1]);
            *(float2*)&g_o[(size_t)l1 * EDIM + h * HD + cc] = make_float2(acc2[nt][2], acc2[nt][3]);
        }
    }
}

// ----------------------------------------------------------------------------
extern "C" void kernel_launch(void* const* d_in, const int* in_sizes, int n_in,
                              void* d_out, int out_size)
{
    const float* X  = (const float*)d_in[0];
    const float* Wq = (const float*)d_in[1];
    const float* bq = (const float*)d_in[2];
    const float* Wk = (const float*)d_in[3];
    const float* bk = (const float*)d_in[4];
    const float* Wv = (const float*)d_in[5];
    const float* bv = (const float*)d_in[6];
    const float* Wo = (const float*)d_in[7];
    const float* bo = (const float*)d_in[8];
    float* out = (float*)d_out;

    (void)in_sizes; (void)n_in; (void)out_size;

    cudaFuncSetAttribute(chunk_attn, cudaFuncAttributeMaxDynamicSharedMemorySize, CHUNK_ATTN_SMEM);

    qkv_gemm<<<dim3(32, 4, 3), 256>>>(X, Wq, bq, Wk, bk, Wv, bv);
    chunk_attn<<<dim3(NC, NH), 256, CHUNK_ATTN_SMEM>>>();
    oproj_gemm<<<dim3(32, 4), 256>>>(Wo, bo, out);
}